// round 9
// baseline (speedup 1.0000x reference)
#include <cuda_runtime.h>
#include <cstdint>

#define NBATCH 4
#define HEADS  16
#define QL     2048
#define KVL    2048
#define HD     64
#define ED     1024
#define K2E    0.045084220027780106f   /* (1/sqrt(1024)) * log2(e) */

#define BQ 256
#define BN 64
#define NCHUNK (KVL / BN)
#define PITCH 68          /* smem pitch (words): %32==4 -> conflict-free frags */

/* scratch: attention output [N, Q, E] fp32 (32 MB) + bit-packed mask (2 MB) */
static __device__ float    g_attn[NBATCH * QL * ED];
static __device__ uint32_t g_maskbits[NBATCH * QL * (KVL / 32)];

/* ----------------------------- small helpers ----------------------------- */
__device__ __forceinline__ uint32_t f2t(float x) {          /* f32 -> tf32 bits */
    uint32_t u;
    asm("cvt.rna.tf32.f32 %0, %1;" : "=r"(u) : "f"(x));
    return u;
}
__device__ __forceinline__ float ex2f(float x) {
    float r;
    asm("ex2.approx.f32 %0, %1;" : "=f"(r) : "f"(x));
    return r;
}
__device__ __forceinline__ uint32_t smem_u32(const void* p) {
    uint32_t a;
    asm("{ .reg .u64 t; cvta.to.shared.u64 t, %1; cvt.u32.u64 %0, t; }"
        : "=r"(a) : "l"(p));
    return a;
}
__device__ __forceinline__ void cp16(uint32_t dst, const void* src) {
    asm volatile("cp.async.cg.shared.global [%0], [%1], 16;"
                 :: "r"(dst), "l"(src) : "memory");
}

/* D(16x8,f32) += A(16x8,tf32) * B(8x8,tf32)  —  m16n8k8 row.col */
__device__ __forceinline__ void mma8(float* d, const uint32_t* a,
                                     uint32_t b0, uint32_t b1) {
    asm volatile(
        "mma.sync.aligned.m16n8k8.row.col.f32.tf32.tf32.f32 "
        "{%0,%1,%2,%3}, {%4,%5,%6,%7}, {%8,%9}, {%0,%1,%2,%3};"
        : "+f"(d[0]), "+f"(d[1]), "+f"(d[2]), "+f"(d[3])
        : "r"(a[0]), "r"(a[1]), "r"(a[2]), "r"(a[3]), "r"(b0), "r"(b1));
}

/* --------------------------- mask bit-packing ---------------------------- */
__global__ void maskpack(const int* __restrict__ M) {
    int warpid = (blockIdx.x * blockDim.x + threadIdx.x) >> 5;
    int lane = threadIdx.x & 31;
    size_t base = (size_t)warpid * 8;
    #pragma unroll
    for (int t = 0; t < 8; t++) {
        size_t wd = base + t;
        int v = M[wd * 32 + lane];
        uint32_t bits = __ballot_sync(0xffffffffu, v != 0);
        if (lane == 0) g_maskbits[wd] = bits;
    }
}

/* -------------------- tf32 mma.sync flash attention ---------------------- */
/* BQ=256, 8 warps; warp w owns q-rows [w*32, w*32+32) = 2 m16 tiles.
   K: cp.async double-buffered raw f32 (mma truncates to tf32).
   QK: ns-tiles in groups of 4, ks-inner -> 8 independent MMAs per step
   (accumulator reuse distance 8 MMAs > HMMA latency, kills dep stalls).    */
__global__ __launch_bounds__(256, 1)
void attn_mma(const float* __restrict__ Q, const float* __restrict__ K,
              const float* __restrict__ V)
{
    extern __shared__ uint32_t sm[];
    uint32_t* KB0 = sm;                     /* [2][64][68] K bufs (raw f32) */
    uint32_t* VS  = sm + 2 * 64 * PITCH;    /* [64][68]    V chunk (tf32)   */
    uint32_t* PH  = sm + 3 * 64 * PITCH;    /* [256][68]   Q staging then P */

    const int tid = threadIdx.x, w = tid >> 5, lane = tid & 31;
    const int g = lane >> 2, c = lane & 3;
    const int n = blockIdx.y >> 4, h = blockIdx.y & 15;
    const int q0 = blockIdx.x * BQ;

    const float* qb = Q + ((size_t)n * QL + q0) * ED + h * HD;
    const float* kb = K + (size_t)n * KVL * ED + h * HD;
    const float* vb = V + (size_t)n * KVL * ED + h * HD;

    const uint32_t kb0s = smem_u32(KB0);

    /* ---- issue cp.async for K chunk 0 immediately (overlaps Q staging) */
    #pragma unroll
    for (int j = 0; j < 4; j++) {
        int flat = tid + 256 * j, r = flat >> 4, d0 = (flat & 15) * 4;
        cp16(kb0s + (r * PITCH + d0) * 4, kb + (size_t)r * ED + d0);
    }
    asm volatile("cp.async.commit_group;" ::: "memory");

    /* ---- stage Q (tf32) into PH [256][68] */
    #pragma unroll
    for (int j = 0; j < 16; j++) {
        int flat = tid + 256 * j, r = flat >> 4, d0 = (flat & 15) * 4;
        float4 v = *(const float4*)(qb + (size_t)r * ED + d0);
        uint32_t* d = PH + r * PITCH + d0;
        d[0] = f2t(v.x); d[1] = f2t(v.y); d[2] = f2t(v.z); d[3] = f2t(v.w);
    }

    /* ---- prefetch V chunk 0 into registers */
    float4 pv[4];
    #pragma unroll
    for (int j = 0; j < 4; j++) {
        int flat = tid + 256 * j, r = flat >> 4, d0 = (flat & 15) * 4;
        pv[j] = *(const float4*)(vb + (size_t)r * ED + d0);
    }
    __syncthreads();

    /* ---- resident Q A-fragments: 2 tiles x 8 ks x 4 regs */
    uint32_t aQ[2][8][4];
    #pragma unroll
    for (int mi = 0; mi < 2; mi++) {
        int rb = w * 32 + mi * 16;
        #pragma unroll
        for (int ks = 0; ks < 8; ks++) {
            const uint32_t* p0 = PH + (rb + g) * PITCH + ks * 8 + c;
            const uint32_t* p1 = p0 + 8 * PITCH;
            aQ[mi][ks][0] = p0[0]; aQ[mi][ks][2] = p0[4];
            aQ[mi][ks][1] = p1[0]; aQ[mi][ks][3] = p1[4];
        }
    }
    __syncthreads();   /* Q frags pulled; PH now reusable as P buffer */

    float Oa[2][8][4];
    #pragma unroll
    for (int mi = 0; mi < 2; mi++)
        #pragma unroll
        for (int i = 0; i < 8; i++)
            #pragma unroll
            for (int j = 0; j < 4; j++) Oa[mi][i][j] = 0.0f;
    float rs00 = 0.0f, rs01 = 0.0f, rs10 = 0.0f, rs11 = 0.0f;

    const unsigned long long* mbase = (const unsigned long long*)g_maskbits;
    const unsigned long long* mp00 = mbase + (size_t)(n * QL + q0 + w * 32 + g) * 32;
    const unsigned long long* mp01 = mp00 + 8 * 32;
    const unsigned long long* mp10 = mp00 + 16 * 32;
    const unsigned long long* mp11 = mp00 + 24 * 32;

    uint32_t* PW = PH + w * 32 * PITCH;    /* per-warp private P buffer */

    for (int ch = 0; ch < NCHUNK; ch++) {
        const int p = ch & 1;
        uint32_t* KS = KB0 + p * 64 * PITCH;
        const bool more = (ch + 1 < NCHUNK);

        __syncthreads();   /* prev chunk's reads of KS[p], VS complete */

        /* stage V(ch) (RNA tf32) from prefetched regs */
        #pragma unroll
        for (int j = 0; j < 4; j++) {
            int flat = tid + 256 * j, r = flat >> 4, d0 = (flat & 15) * 4;
            uint32_t* dv = VS + r * PITCH + d0;
            dv[0] = f2t(pv[j].x); dv[1] = f2t(pv[j].y);
            dv[2] = f2t(pv[j].z); dv[3] = f2t(pv[j].w);
        }

        if (more) {
            /* issue cp.async K(ch+1) into the other buffer */
            const float* kn = kb + (size_t)(ch + 1) * BN * ED;
            const uint32_t kns = kb0s + (1 - p) * 64 * PITCH * 4;
            #pragma unroll
            for (int j = 0; j < 4; j++) {
                int flat = tid + 256 * j, r = flat >> 4, d0 = (flat & 15) * 4;
                cp16(kns + (r * PITCH + d0) * 4, kn + (size_t)r * ED + d0);
            }
            asm volatile("cp.async.commit_group;" ::: "memory");
            /* prefetch V(ch+1) into registers */
            const float* vn = vb + (size_t)(ch + 1) * BN * ED;
            #pragma unroll
            for (int j = 0; j < 4; j++) {
                int flat = tid + 256 * j, r = flat >> 4, d0 = (flat & 15) * 4;
                pv[j] = *(const float4*)(vn + (size_t)r * ED + d0);
            }
            asm volatile("cp.async.wait_group 1;" ::: "memory");
        } else {
            asm volatile("cp.async.wait_group 0;" ::: "memory");
        }
        __syncthreads();   /* V staged + everyone's K(ch) landed */

        unsigned long long m00 = mp00[ch], m01 = mp01[ch];
        unsigned long long m10 = mp10[ch], m11 = mp11[ch];

        /* ---- QK + softmax: ns in groups of 4, ks-inner (8-way MMA ILP) */
        #pragma unroll
        for (int nsg = 0; nsg < 2; nsg++) {
            float S[2][4][4];
            #pragma unroll
            for (int mi = 0; mi < 2; mi++)
                #pragma unroll
                for (int nn = 0; nn < 4; nn++)
                    #pragma unroll
                    for (int j = 0; j < 4; j++) S[mi][nn][j] = 0.0f;

            #pragma unroll
            for (int ks = 0; ks < 8; ks++) {
                #pragma unroll
                for (int nn = 0; nn < 4; nn++) {
                    int ns = nsg * 4 + nn;
                    const uint32_t* bp = KS + (ns * 8 + g) * PITCH + ks * 8 + c;
                    uint32_t b0 = bp[0], b1 = bp[4];
                    mma8(S[0][nn], aQ[0][ks], b0, b1);
                    mma8(S[1][nn], aQ[1][ks], b0, b1);
                }
            }

            #pragma unroll
            for (int nn = 0; nn < 4; nn++) {
                int ns = nsg * 4 + nn;
                int sh = ns * 8 + 2 * c;
                {   /* tile mi = 0 */
                    uint32_t bm0 = (uint32_t)(m00 >> sh);
                    uint32_t bm1 = (uint32_t)(m01 >> sh);
                    float e0 = (bm0 & 1u) ? ex2f(S[0][nn][0] * K2E) : 0.0f;
                    float e1 = (bm0 & 2u) ? ex2f(S[0][nn][1] * K2E) : 0.0f;
                    float e2 = (bm1 & 1u) ? ex2f(S[0][nn][2] * K2E) : 0.0f;
                    float e3 = (bm1 & 2u) ? ex2f(S[0][nn][3] * K2E) : 0.0f;
                    uint32_t h0 = f2t(e0), h1 = f2t(e1);
                    uint32_t h2 = f2t(e2), h3 = f2t(e3);
                    rs00 += __uint_as_float(h0) + __uint_as_float(h1);
                    rs01 += __uint_as_float(h2) + __uint_as_float(h3);
                    uint32_t* d0 = PW + g * PITCH + ns * 8 + 2 * c;
                    uint32_t* d1 = d0 + 8 * PITCH;
                    d0[0] = h0; d0[1] = h1; d1[0] = h2; d1[1] = h3;
                }
                {   /* tile mi = 1 */
                    uint32_t bm0 = (uint32_t)(m10 >> sh);
                    uint32_t bm1 = (uint32_t)(m11 >> sh);
                    float e0 = (bm0 & 1u) ? ex2f(S[1][nn][0] * K2E) : 0.0f;
                    float e1 = (bm0 & 2u) ? ex2f(S[1][nn][1] * K2E) : 0.0f;
                    float e2 = (bm1 & 1u) ? ex2f(S[1][nn][2] * K2E) : 0.0f;
                    float e3 = (bm1 & 2u) ? ex2f(S[1][nn][3] * K2E) : 0.0f;
                    uint32_t h0 = f2t(e0), h1 = f2t(e1);
                    uint32_t h2 = f2t(e2), h3 = f2t(e3);
                    rs10 += __uint_as_float(h0) + __uint_as_float(h1);
                    rs11 += __uint_as_float(h2) + __uint_as_float(h3);
                    uint32_t* d0 = PW + (16 + g) * PITCH + ns * 8 + 2 * c;
                    uint32_t* d1 = d0 + 8 * PITCH;
                    d0[0] = h0; d0[1] = h1; d1[0] = h2; d1[1] = h3;
                }
            }
        }
        __syncwarp();

        /* ---- O += P V : ks-outer, 16 independent MMAs per step */
        #pragma unroll
        for (int ks = 0; ks < 8; ks++) {
            uint32_t aP0[4], aP1[4];
            {
                const uint32_t* p0 = PW + g * PITCH + ks * 8 + c;
                const uint32_t* p1 = p0 + 8 * PITCH;
                aP0[0] = p0[0]; aP0[2] = p0[4];
                aP0[1] = p1[0]; aP0[3] = p1[4];
                const uint32_t* r0p = PW + (16 + g) * PITCH + ks * 8 + c;
                const uint32_t* r1p = r0p + 8 * PITCH;
                aP1[0] = r0p[0]; aP1[2] = r0p[4];
                aP1[1] = r1p[0]; aP1[3] = r1p[4];
            }
            #pragma unroll
            for (int ds = 0; ds < 8; ds++) {
                uint32_t b0 = VS[(ks * 8 + c) * PITCH + ds * 8 + g];
                uint32_t b1 = VS[(ks * 8 + c + 4) * PITCH + ds * 8 + g];
                mma8(Oa[0][ds], aP0, b0, b1);
                mma8(Oa[1][ds], aP1, b0, b1);
            }
        }
    }

    /* row-sum reduce across quad, normalize, write */
    rs00 += __shfl_xor_sync(0xffffffffu, rs00, 1);
    rs00 += __shfl_xor_sync(0xffffffffu, rs00, 2);
    rs01 += __shfl_xor_sync(0xffffffffu, rs01, 1);
    rs01 += __shfl_xor_sync(0xffffffffu, rs01, 2);
    rs10 += __shfl_xor_sync(0xffffffffu, rs10, 1);
    rs10 += __shfl_xor_sync(0xffffffffu, rs10, 2);
    rs11 += __shfl_xor_sync(0xffffffffu, rs11, 1);
    rs11 += __shfl_xor_sync(0xffffffffu, rs11, 2);

    #pragma unroll
    for (int mi = 0; mi < 2; mi++) {
        float inv0 = 1.0f / (mi ? rs10 : rs00);
        float inv1 = 1.0f / (mi ? rs11 : rs01);
        float* ob0 = g_attn
            + (size_t)(n * QL + q0 + w * 32 + mi * 16 + g) * ED + h * HD;
        float* ob1 = ob0 + (size_t)8 * ED;
        #pragma unroll
        for (int ds = 0; ds < 8; ds++) {
            *(float2*)(ob0 + ds * 8 + 2 * c) =
                make_float2(Oa[mi][ds][0] * inv0, Oa[mi][ds][1] * inv0);
            *(float2*)(ob1 + ds * 8 + 2 * c) =
                make_float2(Oa[mi][ds][2] * inv1, Oa[mi][ds][3] * inv1);
        }
    }
}

/* ------------- projection Y = X W^T + b (tf32 mma, plain X) -------------- */
#define PP 36   /* pitch words, PP%32==4 */

__global__ __launch_bounds__(256, 2)
void proj_mma(const float* __restrict__ W, const float* __restrict__ bias,
              float* __restrict__ Y)
{
    extern __shared__ uint32_t ps[];
    uint32_t* XH = ps;                  /* [128][36] */
    uint32_t* WS = ps + 128 * PP;

    const int tid = threadIdx.x, w = tid >> 5, lane = tid & 31;
    const int g = lane >> 2, c = lane & 3;
    const int wm = w & 3, wn = w >> 2;
    const int m0 = blockIdx.y * 128, n0 = blockIdx.x * 128;
    const float* X = g_attn;

    float D[2][8][4];
    #pragma unroll
    for (int a = 0; a < 2; a++)
        #pragma unroll
        for (int i = 0; i < 8; i++)
            #pragma unroll
            for (int j = 0; j < 4; j++) D[a][i][j] = 0.0f;

    for (int kt = 0; kt < 32; kt++) {
        const int k0 = kt * 32;
        __syncthreads();
        #pragma unroll
        for (int j = 0; j < 4; j++) {
            int flat = tid + 256 * j, r = flat >> 3, c4 = flat & 7;
            float4 xv = *(const float4*)(X + (size_t)(m0 + r) * ED + k0 + c4 * 4);
            uint32_t* dh = XH + r * PP + c4 * 4;
            dh[0] = f2t(xv.x); dh[1] = f2t(xv.y);
            dh[2] = f2t(xv.z); dh[3] = f2t(xv.w);
            float4 wv = *(const float4*)(W + (size_t)(n0 + r) * ED + k0 + c4 * 4);
            uint32_t* dw = WS + r * PP + c4 * 4;
            dw[0] = f2t(wv.x); dw[1] = f2t(wv.y);
            dw[2] = f2t(wv.z); dw[3] = f2t(wv.w);
        }
        __syncthreads();

        #pragma unroll
        for (int ks = 0; ks < 4; ks++) {
            uint32_t A[2][4];
            #pragma unroll
            for (int mi = 0; mi < 2; mi++) {
                int rb = wm * 32 + mi * 16;
                const uint32_t* p0 = XH + (rb + g) * PP + ks * 8 + c;
                const uint32_t* p1 = XH + (rb + g + 8) * PP + ks * 8 + c;
                A[mi][0] = p0[0]; A[mi][2] = p0[4];
                A[mi][1] = p1[0]; A[mi][3] = p1[4];
            }
            #pragma unroll
            for (int ns = 0; ns < 8; ns++) {
                const uint32_t* bp = WS + (wn * 64 + ns * 8 + g) * PP + ks * 8 + c;
                uint32_t b0 = bp[0], b1 = bp[4];
                mma8(D[0][ns], A[0], b0, b1);
                mma8(D[1][ns], A[1], b0, b1);
            }
        }
    }

    #pragma unroll
    for (int mi = 0; mi < 2; mi++) {
        int row0 = m0 + wm * 32 + mi * 16 + g;
        #pragma unroll
        for (int ns = 0; ns < 8; ns++) {
            int col = n0 + wn * 64 + ns * 8 + 2 * c;
            float2 bv = *(const float2*)(bias + col);
            *(float2*)(Y + (size_t)row0 * ED + col) =
                make_float2(D[mi][ns][0] + bv.x, D[mi][ns][1] + bv.y);
            *(float2*)(Y + (size_t)(row0 + 8) * ED + col) =
                make_float2(D[mi][ns][2] + bv.x, D[mi][ns][3] + bv.y);
        }
    }
}

/* --------------------------------- launch -------------------------------- */
extern "C" void kernel_launch(void* const* d_in, const int* in_sizes, int n_in,
                              void* d_out, int out_size)
{
    const float* q    = (const float*)d_in[0];
    const float* k    = (const float*)d_in[1];
    const float* v    = (const float*)d_in[2];
    const int*   mask = (const int*)  d_in[3];
    const float* W    = (const float*)d_in[4];
    const float* b    = (const float*)d_in[5];
    float* out = (float*)d_out;

    const int smem_attn = (3 * 64 + 256) * PITCH * 4;   /* 121856 */
    const int smem_proj = 2 * 128 * PP * 4;             /* 36864  */
    cudaFuncSetAttribute(attn_mma, cudaFuncAttributeMaxDynamicSharedMemorySize, smem_attn);
    cudaFuncSetAttribute(proj_mma, cudaFuncAttributeMaxDynamicSharedMemorySize, smem_proj);

    maskpack<<<8192, 256>>>(mask);

    dim3 g1(QL / BQ, NBATCH * HEADS);
    attn_mma<<<g1, 256, smem_attn>>>(q, k, v);

    dim3 g2(ED / 128, (NBATCH * QL) / 128);
    proj_mma<<<g2, 256, smem_proj>>>(W, b, out);
}

// round 10
// speedup vs baseline: 1.5024x; 1.5024x over previous
#include <cuda_runtime.h>
#include <cuda_fp16.h>
#include <cstdint>

#define NBATCH 4
#define HEADS  16
#define QL     2048
#define KVL    2048
#define HD     64
#define ED     1024
#define K2E    0.045084220027780106f   /* (1/sqrt(1024)) * log2(e) */

#define BQ 256
#define BN 64
#define NCHUNK (KVL / BN)
#define PH_PITCH 36   /* words (half2 pairs); %32==4 -> conflict-free frags */

/* scratch: attention output [N, Q, E] fp32 (32 MB) + bit-packed mask (2 MB) */
static __device__ float    g_attn[NBATCH * QL * ED];
static __device__ uint32_t g_maskbits[NBATCH * QL * (KVL / 32)];

/* ----------------------------- small helpers ----------------------------- */
__device__ __forceinline__ uint32_t pack2(float lo, float hi) {
    __half2 h = __floats2half2_rn(lo, hi);
    return *(uint32_t*)&h;
}
__device__ __forceinline__ float ex2f(float x) {
    float r;
    asm("ex2.approx.f32 %0, %1;" : "=f"(r) : "f"(x));
    return r;
}

/* D(16x8,f32) += A(16x16,f16) * B(16x8,f16)  —  m16n8k16 row.col */
__device__ __forceinline__ void mma16(float* d, const uint32_t* a,
                                      uint32_t b0, uint32_t b1) {
    asm volatile(
        "mma.sync.aligned.m16n8k16.row.col.f32.f16.f16.f32 "
        "{%0,%1,%2,%3}, {%4,%5,%6,%7}, {%8,%9}, {%0,%1,%2,%3};"
        : "+f"(d[0]), "+f"(d[1]), "+f"(d[2]), "+f"(d[3])
        : "r"(a[0]), "r"(a[1]), "r"(a[2]), "r"(a[3]), "r"(b0), "r"(b1));
}

/* --------------------------- mask bit-packing ---------------------------- */
__global__ void maskpack(const int* __restrict__ M) {
    int warpid = (blockIdx.x * blockDim.x + threadIdx.x) >> 5;
    int lane = threadIdx.x & 31;
    size_t base = (size_t)warpid * 8;
    #pragma unroll
    for (int t = 0; t < 8; t++) {
        size_t wd = base + t;
        int v = M[wd * 32 + lane];
        uint32_t bits = __ballot_sync(0xffffffffu, v != 0);
        if (lane == 0) g_maskbits[wd] = bits;
    }
}

/* -------------------- fp16 mma.sync flash attention ---------------------- */
/* BQ=256, 8 warps; warp w owns q-rows [w*32, w*32+32) = 2 m16 tiles.
   All operands fp16 (same 10-bit mantissa as tf32), fp32 accum.
   K smem [kv][d-half2], Vt smem [d][kv-half2] (transposed at staging),
   pitch 36 words -> all fragment LDS conflict-free.                         */
__global__ __launch_bounds__(256, 1)
void attn_mma(const float* __restrict__ Q, const float* __restrict__ K,
              const float* __restrict__ V)
{
    extern __shared__ uint32_t sm[];
    uint32_t* KS = sm;                          /* [64][36]  K  (half2)    */
    uint32_t* VS = sm + 64 * PH_PITCH;          /* [64][36]  Vt (half2)    */
    uint32_t* PH = sm + 2 * 64 * PH_PITCH;      /* [256][36] Q then P      */

    const int tid = threadIdx.x, w = tid >> 5, lane = tid & 31;
    const int g = lane >> 2, c = lane & 3;
    const int n = blockIdx.y >> 4, h = blockIdx.y & 15;
    const int q0 = blockIdx.x * BQ;

    const float* qb = Q + ((size_t)n * QL + q0) * ED + h * HD;
    const float* kb = K + (size_t)n * KVL * ED + h * HD;
    const float* vb = V + (size_t)n * KVL * ED + h * HD;

    /* ---- stage Q (fp16) into PH [256 rows][32 data words] */
    #pragma unroll
    for (int j = 0; j < 16; j++) {
        int flat = tid + 256 * j, r = flat >> 4, d0 = (flat & 15) * 4;
        float4 v = *(const float4*)(qb + (size_t)r * ED + d0);
        uint32_t* d = PH + r * PH_PITCH + d0 / 2;
        d[0] = pack2(v.x, v.y); d[1] = pack2(v.z, v.w);
    }

    /* ---- stage K chunk 0: rows kv, words = d pairs */
    float4 pk[4];
    #pragma unroll
    for (int j = 0; j < 4; j++) {
        int flat = tid + 256 * j, r = flat >> 4, d0 = (flat & 15) * 4;
        float4 kv4 = *(const float4*)(kb + (size_t)r * ED + d0);
        uint32_t* dk = KS + r * PH_PITCH + d0 / 2;
        dk[0] = pack2(kv4.x, kv4.y); dk[1] = pack2(kv4.z, kv4.w);
        pk[j] = kv4; /* keep regs warm; overwritten by prefetch below */
    }
    /* ---- stage Vt chunk 0: word (d, rp) = {V[2rp][d], V[2rp+1][d]} */
    const int rp = lane;                 /* kv row-pair index, 0..31 */
    float4 pva[2], pvb[2];
    #pragma unroll
    for (int j = 0; j < 2; j++) {
        int d0 = (w + 8 * j) * 4;
        pva[j] = *(const float4*)(vb + (size_t)(2 * rp) * ED + d0);
        pvb[j] = *(const float4*)(vb + (size_t)(2 * rp + 1) * ED + d0);
        float a4[4] = {pva[j].x, pva[j].y, pva[j].z, pva[j].w};
        float b4[4] = {pvb[j].x, pvb[j].y, pvb[j].z, pvb[j].w};
        #pragma unroll
        for (int e = 0; e < 4; e++)
            VS[(d0 + e) * PH_PITCH + rp] = pack2(a4[e], b4[e]);
    }
    __syncthreads();

    /* ---- resident Q A-fragments: 2 tiles x 4 ks16 x 4 regs */
    uint32_t aQ[2][4][4];
    #pragma unroll
    for (int mi = 0; mi < 2; mi++) {
        int rb = w * 32 + mi * 16;
        #pragma unroll
        for (int ks = 0; ks < 4; ks++) {
            const uint32_t* p0 = PH + (rb + g) * PH_PITCH + ks * 8 + c;
            const uint32_t* p1 = p0 + 8 * PH_PITCH;
            aQ[mi][ks][0] = p0[0]; aQ[mi][ks][2] = p0[4];
            aQ[mi][ks][1] = p1[0]; aQ[mi][ks][3] = p1[4];
        }
    }
    __syncthreads();   /* Q frags pulled; PH reusable as P buffer */

    float Oa[2][8][4];
    #pragma unroll
    for (int mi = 0; mi < 2; mi++)
        #pragma unroll
        for (int i = 0; i < 8; i++)
            #pragma unroll
            for (int j = 0; j < 4; j++) Oa[mi][i][j] = 0.0f;
    float rs00 = 0.0f, rs01 = 0.0f, rs10 = 0.0f, rs11 = 0.0f;

    const unsigned long long* mbase = (const unsigned long long*)g_maskbits;
    const unsigned long long* mp00 = mbase + (size_t)(n * QL + q0 + w * 32 + g) * 32;
    const unsigned long long* mp01 = mp00 + 8 * 32;
    const unsigned long long* mp10 = mp00 + 16 * 32;
    const unsigned long long* mp11 = mp00 + 24 * 32;

    uint32_t* PW = PH + w * 32 * PH_PITCH;   /* per-warp 32-row P buffer */

    for (int ch = 0; ch < NCHUNK; ch++) {
        const bool more = (ch + 1 < NCHUNK);

        /* prefetch chunk ch+1 into registers (lands during QK below) */
        if (more) {
            const float* kn = kb + (size_t)(ch + 1) * BN * ED;
            const float* vn = vb + (size_t)(ch + 1) * BN * ED;
            #pragma unroll
            for (int j = 0; j < 4; j++) {
                int flat = tid + 256 * j, r = flat >> 4, d0 = (flat & 15) * 4;
                pk[j] = *(const float4*)(kn + (size_t)r * ED + d0);
            }
            #pragma unroll
            for (int j = 0; j < 2; j++) {
                int d0 = (w + 8 * j) * 4;
                pva[j] = *(const float4*)(vn + (size_t)(2 * rp) * ED + d0);
                pvb[j] = *(const float4*)(vn + (size_t)(2 * rp + 1) * ED + d0);
            }
        }

        unsigned long long m00 = mp00[ch], m01 = mp01[ch];
        unsigned long long m10 = mp10[ch], m11 = mp11[ch];

        /* ---- QK + softmax: ns-pairs, ks-inner (4-deep MMA ILP) */
        #pragma unroll
        for (int nsp = 0; nsp < 4; nsp++) {
            float S[2][2][4];
            #pragma unroll
            for (int mi = 0; mi < 2; mi++)
                #pragma unroll
                for (int nn = 0; nn < 2; nn++)
                    #pragma unroll
                    for (int j = 0; j < 4; j++) S[mi][nn][j] = 0.0f;

            #pragma unroll
            for (int ks = 0; ks < 4; ks++) {
                #pragma unroll
                for (int nn = 0; nn < 2; nn++) {
                    int ns = nsp * 2 + nn;
                    const uint32_t* bp = KS + (ns * 8 + g) * PH_PITCH + ks * 8 + c;
                    uint32_t b0 = bp[0], b1 = bp[4];
                    mma16(S[0][nn], aQ[0][ks], b0, b1);
                    mma16(S[1][nn], aQ[1][ks], b0, b1);
                }
            }

            #pragma unroll
            for (int nn = 0; nn < 2; nn++) {
                int ns = nsp * 2 + nn;
                int sh = ns * 8 + 2 * c;
                {   /* tile mi = 0 */
                    uint32_t bm0 = (uint32_t)(m00 >> sh);
                    uint32_t bm1 = (uint32_t)(m01 >> sh);
                    float e0 = (bm0 & 1u) ? ex2f(S[0][nn][0] * K2E) : 0.0f;
                    float e1 = (bm0 & 2u) ? ex2f(S[0][nn][1] * K2E) : 0.0f;
                    float e2 = (bm1 & 1u) ? ex2f(S[0][nn][2] * K2E) : 0.0f;
                    float e3 = (bm1 & 2u) ? ex2f(S[0][nn][3] * K2E) : 0.0f;
                    rs00 += e0 + e1;
                    rs01 += e2 + e3;
                    PW[g * PH_PITCH + ns * 4 + c]       = pack2(e0, e1);
                    PW[(g + 8) * PH_PITCH + ns * 4 + c] = pack2(e2, e3);
                }
                {   /* tile mi = 1 */
                    uint32_t bm0 = (uint32_t)(m10 >> sh);
                    uint32_t bm1 = (uint32_t)(m11 >> sh);
                    float e0 = (bm0 & 1u) ? ex2f(S[1][nn][0] * K2E) : 0.0f;
                    float e1 = (bm0 & 2u) ? ex2f(S[1][nn][1] * K2E) : 0.0f;
                    float e2 = (bm1 & 1u) ? ex2f(S[1][nn][2] * K2E) : 0.0f;
                    float e3 = (bm1 & 2u) ? ex2f(S[1][nn][3] * K2E) : 0.0f;
                    rs10 += e0 + e1;
                    rs11 += e2 + e3;
                    PW[(16 + g) * PH_PITCH + ns * 4 + c] = pack2(e0, e1);
                    PW[(24 + g) * PH_PITCH + ns * 4 + c] = pack2(e2, e3);
                }
            }
        }
        __syncwarp();

        /* ---- O += P V : ks16-outer, 16 independent MMAs per step */
        #pragma unroll
        for (int ks = 0; ks < 4; ks++) {
            uint32_t aP0[4], aP1[4];
            {
                const uint32_t* p0 = PW + g * PH_PITCH + ks * 8 + c;
                const uint32_t* p1 = p0 + 8 * PH_PITCH;
                aP0[0] = p0[0]; aP0[2] = p0[4];
                aP0[1] = p1[0]; aP0[3] = p1[4];
                const uint32_t* r0p = PW + (16 + g) * PH_PITCH + ks * 8 + c;
                const uint32_t* r1p = r0p + 8 * PH_PITCH;
                aP1[0] = r0p[0]; aP1[2] = r0p[4];
                aP1[1] = r1p[0]; aP1[3] = r1p[4];
            }
            #pragma unroll
            for (int ds = 0; ds < 8; ds++) {
                const uint32_t* vp = VS + (ds * 8 + g) * PH_PITCH + ks * 8 + c;
                uint32_t b0 = vp[0], b1 = vp[4];
                mma16(Oa[0][ds], aP0, b0, b1);
                mma16(Oa[1][ds], aP1, b0, b1);
            }
        }

        /* ---- stage chunk ch+1 (K rows, Vt transposed) */
        __syncthreads();   /* all reads of KS/VS done */
        if (more) {
            #pragma unroll
            for (int j = 0; j < 4; j++) {
                int flat = tid + 256 * j, r = flat >> 4, d0 = (flat & 15) * 4;
                uint32_t* dk = KS + r * PH_PITCH + d0 / 2;
                dk[0] = pack2(pk[j].x, pk[j].y);
                dk[1] = pack2(pk[j].z, pk[j].w);
            }
            #pragma unroll
            for (int j = 0; j < 2; j++) {
                int d0 = (w + 8 * j) * 4;
                float a4[4] = {pva[j].x, pva[j].y, pva[j].z, pva[j].w};
                float b4[4] = {pvb[j].x, pvb[j].y, pvb[j].z, pvb[j].w};
                #pragma unroll
                for (int e = 0; e < 4; e++)
                    VS[(d0 + e) * PH_PITCH + rp] = pack2(a4[e], b4[e]);
            }
            __syncthreads();   /* staged data visible for next iteration */
        }
    }

    /* row-sum reduce across quad, normalize, write */
    rs00 += __shfl_xor_sync(0xffffffffu, rs00, 1);
    rs00 += __shfl_xor_sync(0xffffffffu, rs00, 2);
    rs01 += __shfl_xor_sync(0xffffffffu, rs01, 1);
    rs01 += __shfl_xor_sync(0xffffffffu, rs01, 2);
    rs10 += __shfl_xor_sync(0xffffffffu, rs10, 1);
    rs10 += __shfl_xor_sync(0xffffffffu, rs10, 2);
    rs11 += __shfl_xor_sync(0xffffffffu, rs11, 1);
    rs11 += __shfl_xor_sync(0xffffffffu, rs11, 2);

    #pragma unroll
    for (int mi = 0; mi < 2; mi++) {
        float inv0 = 1.0f / (mi ? rs10 : rs00);
        float inv1 = 1.0f / (mi ? rs11 : rs01);
        float* ob0 = g_attn
            + (size_t)(n * QL + q0 + w * 32 + mi * 16 + g) * ED + h * HD;
        float* ob1 = ob0 + (size_t)8 * ED;
        #pragma unroll
        for (int ds = 0; ds < 8; ds++) {
            *(float2*)(ob0 + ds * 8 + 2 * c) =
                make_float2(Oa[mi][ds][0] * inv0, Oa[mi][ds][1] * inv0);
            *(float2*)(ob1 + ds * 8 + 2 * c) =
                make_float2(Oa[mi][ds][2] * inv1, Oa[mi][ds][3] * inv1);
        }
    }
}

/* ------------- projection Y = X W^T + b (fp16 mma, f32 accum) ------------ */
__global__ __launch_bounds__(256, 2)
void proj_mma(const float* __restrict__ W, const float* __restrict__ bias,
              float* __restrict__ Y)
{
    extern __shared__ uint32_t ps[];
    uint32_t* XH = ps;                       /* [128][36] half2 */
    uint32_t* WS = ps + 128 * PH_PITCH;

    const int tid = threadIdx.x, w = tid >> 5, lane = tid & 31;
    const int g = lane >> 2, c = lane & 3;
    const int wm = w & 3, wn = w >> 2;
    const int m0 = blockIdx.y * 128, n0 = blockIdx.x * 128;
    const float* X = g_attn;

    float D[2][8][4];
    #pragma unroll
    for (int a = 0; a < 2; a++)
        #pragma unroll
        for (int i = 0; i < 8; i++)
            #pragma unroll
            for (int j = 0; j < 4; j++) D[a][i][j] = 0.0f;

    for (int kt = 0; kt < 32; kt++) {
        const int k0 = kt * 32;
        __syncthreads();
        #pragma unroll
        for (int j = 0; j < 4; j++) {
            int flat = tid + 256 * j, r = flat >> 3, c4 = flat & 7;
            float4 xv = *(const float4*)(X + (size_t)(m0 + r) * ED + k0 + c4 * 4);
            uint32_t* dh = XH + r * PH_PITCH + c4 * 2;
            dh[0] = pack2(xv.x, xv.y); dh[1] = pack2(xv.z, xv.w);
            float4 wv = *(const float4*)(W + (size_t)(n0 + r) * ED + k0 + c4 * 4);
            uint32_t* dw = WS + r * PH_PITCH + c4 * 2;
            dw[0] = pack2(wv.x, wv.y); dw[1] = pack2(wv.z, wv.w);
        }
        __syncthreads();

        #pragma unroll
        for (int ks = 0; ks < 2; ks++) {
            uint32_t A[2][4];
            #pragma unroll
            for (int mi = 0; mi < 2; mi++) {
                int rb = wm * 32 + mi * 16;
                const uint32_t* p0 = XH + (rb + g) * PH_PITCH + ks * 8 + c;
                const uint32_t* p1 = XH + (rb + g + 8) * PH_PITCH + ks * 8 + c;
                A[mi][0] = p0[0]; A[mi][2] = p0[4];
                A[mi][1] = p1[0]; A[mi][3] = p1[4];
            }
            #pragma unroll
            for (int ns = 0; ns < 8; ns++) {
                const uint32_t* bp =
                    WS + (wn * 64 + ns * 8 + g) * PH_PITCH + ks * 8 + c;
                uint32_t b0 = bp[0], b1 = bp[4];
                mma16(D[0][ns], A[0], b0, b1);
                mma16(D[1][ns], A[1], b0, b1);
            }
        }
    }

    #pragma unroll
    for (int mi = 0; mi < 2; mi++) {
        int row0 = m0 + wm * 32 + mi * 16 + g;
        #pragma unroll
        for (int ns = 0; ns < 8; ns++) {
            int col = n0 + wn * 64 + ns * 8 + 2 * c;
            float2 bv = *(const float2*)(bias + col);
            *(float2*)(Y + (size_t)row0 * ED + col) =
                make_float2(D[mi][ns][0] + bv.x, D[mi][ns][1] + bv.y);
            *(float2*)(Y + (size_t)(row0 + 8) * ED + col) =
                make_float2(D[mi][ns][2] + bv.x, D[mi][ns][3] + bv.y);
        }
    }
}

/* --------------------------------- launch -------------------------------- */
extern "C" void kernel_launch(void* const* d_in, const int* in_sizes, int n_in,
                              void* d_out, int out_size)
{
    const float* q    = (const float*)d_in[0];
    const float* k    = (const float*)d_in[1];
    const float* v    = (const float*)d_in[2];
    const int*   mask = (const int*)  d_in[3];
    const float* W    = (const float*)d_in[4];
    const float* b    = (const float*)d_in[5];
    float* out = (float*)d_out;

    const int smem_attn = (2 * 64 + 256) * PH_PITCH * 4;   /* 55296 */
    const int smem_proj = 2 * 128 * PH_PITCH * 4;          /* 36864 */
    cudaFuncSetAttribute(attn_mma, cudaFuncAttributeMaxDynamicSharedMemorySize, smem_attn);
    cudaFuncSetAttribute(proj_mma, cudaFuncAttributeMaxDynamicSharedMemorySize, smem_proj);

    maskpack<<<8192, 256>>>(mask);

    dim3 g1(QL / BQ, NBATCH * HEADS);
    attn_mma<<<g1, 256, smem_attn>>>(q, k, v);

    dim3 g2(ED / 128, (NBATCH * QL) / 128);
    proj_mma<<<g2, 256, smem_proj>>>(W, b, out);
}

// round 11
// speedup vs baseline: 1.6043x; 1.0678x over previous
#include <cuda_runtime.h>
#include <cuda_fp16.h>
#include <cstdint>

#define NBATCH 4
#define HEADS  16
#define QL     2048
#define KVL    2048
#define HD     64
#define ED     1024
#define K2E    0.045084220027780106f   /* (1/sqrt(1024)) * log2(e) */

#define BQ 256
#define BN 64
#define NCHUNK (KVL / BN)
#define PH_PITCH 36   /* words (half2 pairs); %32==4 -> conflict-free frags */

/* scratch: attention output [N, Q, E] fp32 (32 MB) + bit-packed mask (2 MB) */
static __device__ float    g_attn[NBATCH * QL * ED];
static __device__ uint32_t g_maskbits[NBATCH * QL * (KVL / 32)];

/* ----------------------------- small helpers ----------------------------- */
__device__ __forceinline__ uint32_t pack2(float lo, float hi) {
    __half2 h = __floats2half2_rn(lo, hi);
    return *(uint32_t*)&h;
}
__device__ __forceinline__ float ex2f(float x) {
    float r;
    asm("ex2.approx.f32 %0, %1;" : "=f"(r) : "f"(x));
    return r;
}

/* D(16x8,f32) += A(16x16,f16) * B(16x8,f16)  —  m16n8k16 row.col */
__device__ __forceinline__ void mma16(float* d, const uint32_t* a,
                                      uint32_t b0, uint32_t b1) {
    asm volatile(
        "mma.sync.aligned.m16n8k16.row.col.f32.f16.f16.f32 "
        "{%0,%1,%2,%3}, {%4,%5,%6,%7}, {%8,%9}, {%0,%1,%2,%3};"
        : "+f"(d[0]), "+f"(d[1]), "+f"(d[2]), "+f"(d[3])
        : "r"(a[0]), "r"(a[1]), "r"(a[2]), "r"(a[3]), "r"(b0), "r"(b1));
}

/* --------------------------- mask bit-packing ---------------------------- */
__global__ void maskpack(const int* __restrict__ M) {
    int warpid = (blockIdx.x * blockDim.x + threadIdx.x) >> 5;
    int lane = threadIdx.x & 31;
    size_t base = (size_t)warpid * 8;
    #pragma unroll
    for (int t = 0; t < 8; t++) {
        size_t wd = base + t;
        int v = M[wd * 32 + lane];
        uint32_t bits = __ballot_sync(0xffffffffu, v != 0);
        if (lane == 0) g_maskbits[wd] = bits;
    }
}

/* -------------------- fp16 mma.sync flash attention ---------------------- */
/* BQ=256, 8 warps; warp w owns q-rows [w*32, w*32+32) = 2 m16 tiles.
   KEY: QK D-fragment layout == PV A-fragment layout (per 2 ns-tiles), so P
   stays in registers — no smem round trip, no syncwarp. Per nsp (16 kv):
   QK(16 MMAs) -> exp/pack -> PV(16 MMAs), all register-resident.           */
__global__ __launch_bounds__(256, 1)
void attn_mma(const float* __restrict__ Q, const float* __restrict__ K,
              const float* __restrict__ V)
{
    extern __shared__ uint32_t sm[];
    uint32_t* KS = sm;                          /* [64][36]  K  (half2)    */
    uint32_t* VS = sm + 64 * PH_PITCH;          /* [64][36]  Vt (half2)    */
    uint32_t* PH = sm + 2 * 64 * PH_PITCH;      /* [256][36] Q staging     */

    const int tid = threadIdx.x, w = tid >> 5, lane = tid & 31;
    const int g = lane >> 2, c = lane & 3;
    const int n = blockIdx.y >> 4, h = blockIdx.y & 15;
    const int q0 = blockIdx.x * BQ;

    const float* qb = Q + ((size_t)n * QL + q0) * ED + h * HD;
    const float* kb = K + (size_t)n * KVL * ED + h * HD;
    const float* vb = V + (size_t)n * KVL * ED + h * HD;

    /* ---- stage Q (fp16) into PH [256 rows][32 data words] */
    #pragma unroll
    for (int j = 0; j < 16; j++) {
        int flat = tid + 256 * j, r = flat >> 4, d0 = (flat & 15) * 4;
        float4 v = *(const float4*)(qb + (size_t)r * ED + d0);
        uint32_t* d = PH + r * PH_PITCH + d0 / 2;
        d[0] = pack2(v.x, v.y); d[1] = pack2(v.z, v.w);
    }

    /* ---- stage K chunk 0: rows kv, words = d pairs */
    float4 pk[4];
    #pragma unroll
    for (int j = 0; j < 4; j++) {
        int flat = tid + 256 * j, r = flat >> 4, d0 = (flat & 15) * 4;
        float4 kv4 = *(const float4*)(kb + (size_t)r * ED + d0);
        uint32_t* dk = KS + r * PH_PITCH + d0 / 2;
        dk[0] = pack2(kv4.x, kv4.y); dk[1] = pack2(kv4.z, kv4.w);
        pk[j] = kv4;
    }
    /* ---- stage Vt chunk 0: word (d, rp) = {V[2rp][d], V[2rp+1][d]} */
    const int rp = lane;                 /* kv row-pair index, 0..31 */
    float4 pva[2], pvb[2];
    #pragma unroll
    for (int j = 0; j < 2; j++) {
        int d0 = (w + 8 * j) * 4;
        pva[j] = *(const float4*)(vb + (size_t)(2 * rp) * ED + d0);
        pvb[j] = *(const float4*)(vb + (size_t)(2 * rp + 1) * ED + d0);
        float a4[4] = {pva[j].x, pva[j].y, pva[j].z, pva[j].w};
        float b4[4] = {pvb[j].x, pvb[j].y, pvb[j].z, pvb[j].w};
        #pragma unroll
        for (int e = 0; e < 4; e++)
            VS[(d0 + e) * PH_PITCH + rp] = pack2(a4[e], b4[e]);
    }
    __syncthreads();

    /* ---- resident Q A-fragments: 2 tiles x 4 ks16 x 4 regs */
    uint32_t aQ[2][4][4];
    #pragma unroll
    for (int mi = 0; mi < 2; mi++) {
        int rb = w * 32 + mi * 16;
        #pragma unroll
        for (int ks = 0; ks < 4; ks++) {
            const uint32_t* p0 = PH + (rb + g) * PH_PITCH + ks * 8 + c;
            const uint32_t* p1 = p0 + 8 * PH_PITCH;
            aQ[mi][ks][0] = p0[0]; aQ[mi][ks][2] = p0[4];
            aQ[mi][ks][1] = p1[0]; aQ[mi][ks][3] = p1[4];
        }
    }

    float Oa[2][8][4];
    #pragma unroll
    for (int mi = 0; mi < 2; mi++)
        #pragma unroll
        for (int i = 0; i < 8; i++)
            #pragma unroll
            for (int j = 0; j < 4; j++) Oa[mi][i][j] = 0.0f;
    float rs00 = 0.0f, rs01 = 0.0f, rs10 = 0.0f, rs11 = 0.0f;

    const unsigned long long* mbase = (const unsigned long long*)g_maskbits;
    const unsigned long long* mp00 = mbase + (size_t)(n * QL + q0 + w * 32 + g) * 32;
    const unsigned long long* mp01 = mp00 + 8 * 32;
    const unsigned long long* mp10 = mp00 + 16 * 32;
    const unsigned long long* mp11 = mp00 + 24 * 32;

    for (int ch = 0; ch < NCHUNK; ch++) {
        const bool more = (ch + 1 < NCHUNK);

        /* prefetch chunk ch+1 into registers (lands during QK below) */
        if (more) {
            const float* kn = kb + (size_t)(ch + 1) * BN * ED;
            const float* vn = vb + (size_t)(ch + 1) * BN * ED;
            #pragma unroll
            for (int j = 0; j < 4; j++) {
                int flat = tid + 256 * j, r = flat >> 4, d0 = (flat & 15) * 4;
                pk[j] = *(const float4*)(kn + (size_t)r * ED + d0);
            }
            #pragma unroll
            for (int j = 0; j < 2; j++) {
                int d0 = (w + 8 * j) * 4;
                pva[j] = *(const float4*)(vn + (size_t)(2 * rp) * ED + d0);
                pvb[j] = *(const float4*)(vn + (size_t)(2 * rp + 1) * ED + d0);
            }
        }

        unsigned long long m00 = mp00[ch], m01 = mp01[ch];
        unsigned long long m10 = mp10[ch], m11 = mp11[ch];

        /* ---- per nsp (16 kv): QK -> softmax (registers) -> PV */
        #pragma unroll
        for (int nsp = 0; nsp < 4; nsp++) {
            float S[2][2][4];
            #pragma unroll
            for (int mi = 0; mi < 2; mi++)
                #pragma unroll
                for (int nn = 0; nn < 2; nn++)
                    #pragma unroll
                    for (int j = 0; j < 4; j++) S[mi][nn][j] = 0.0f;

            #pragma unroll
            for (int ks = 0; ks < 4; ks++) {
                #pragma unroll
                for (int nn = 0; nn < 2; nn++) {
                    int ns = nsp * 2 + nn;
                    const uint32_t* bp = KS + (ns * 8 + g) * PH_PITCH + ks * 8 + c;
                    uint32_t b0 = bp[0], b1 = bp[4];
                    mma16(S[0][nn], aQ[0][ks], b0, b1);
                    mma16(S[1][nn], aQ[1][ks], b0, b1);
                }
            }

            /* softmax -> P A-fragments directly in registers:
               aP[mi] = {pack(e0,e1)@nn0, pack(e2,e3)@nn0,
                         pack(e0,e1)@nn1, pack(e2,e3)@nn1}                 */
            uint32_t aP0[4], aP1[4];
            #pragma unroll
            for (int nn = 0; nn < 2; nn++) {
                int ns = nsp * 2 + nn;
                int sh = ns * 8 + 2 * c;
                {   /* tile mi = 0 */
                    uint32_t bm0 = (uint32_t)(m00 >> sh);
                    uint32_t bm1 = (uint32_t)(m01 >> sh);
                    float e0 = (bm0 & 1u) ? ex2f(S[0][nn][0] * K2E) : 0.0f;
                    float e1 = (bm0 & 2u) ? ex2f(S[0][nn][1] * K2E) : 0.0f;
                    float e2 = (bm1 & 1u) ? ex2f(S[0][nn][2] * K2E) : 0.0f;
                    float e3 = (bm1 & 2u) ? ex2f(S[0][nn][3] * K2E) : 0.0f;
                    rs00 += e0 + e1;
                    rs01 += e2 + e3;
                    aP0[2 * nn]     = pack2(e0, e1);
                    aP0[2 * nn + 1] = pack2(e2, e3);
                }
                {   /* tile mi = 1 */
                    uint32_t bm0 = (uint32_t)(m10 >> sh);
                    uint32_t bm1 = (uint32_t)(m11 >> sh);
                    float e0 = (bm0 & 1u) ? ex2f(S[1][nn][0] * K2E) : 0.0f;
                    float e1 = (bm0 & 2u) ? ex2f(S[1][nn][1] * K2E) : 0.0f;
                    float e2 = (bm1 & 1u) ? ex2f(S[1][nn][2] * K2E) : 0.0f;
                    float e3 = (bm1 & 2u) ? ex2f(S[1][nn][3] * K2E) : 0.0f;
                    rs10 += e0 + e1;
                    rs11 += e2 + e3;
                    aP1[2 * nn]     = pack2(e0, e1);
                    aP1[2 * nn + 1] = pack2(e2, e3);
                }
            }

            /* ---- O += P V for this 16-kv slice (B frags from Vt smem) */
            #pragma unroll
            for (int ds = 0; ds < 8; ds++) {
                const uint32_t* vp = VS + (ds * 8 + g) * PH_PITCH + nsp * 8 + c;
                uint32_t b0 = vp[0], b1 = vp[4];
                mma16(Oa[0][ds], aP0, b0, b1);
                mma16(Oa[1][ds], aP1, b0, b1);
            }
        }

        /* ---- stage chunk ch+1 (K rows, Vt transposed) */
        __syncthreads();   /* all reads of KS/VS done */
        if (more) {
            #pragma unroll
            for (int j = 0; j < 4; j++) {
                int flat = tid + 256 * j, r = flat >> 4, d0 = (flat & 15) * 4;
                uint32_t* dk = KS + r * PH_PITCH + d0 / 2;
                dk[0] = pack2(pk[j].x, pk[j].y);
                dk[1] = pack2(pk[j].z, pk[j].w);
            }
            #pragma unroll
            for (int j = 0; j < 2; j++) {
                int d0 = (w + 8 * j) * 4;
                float a4[4] = {pva[j].x, pva[j].y, pva[j].z, pva[j].w};
                float b4[4] = {pvb[j].x, pvb[j].y, pvb[j].z, pvb[j].w};
                #pragma unroll
                for (int e = 0; e < 4; e++)
                    VS[(d0 + e) * PH_PITCH + rp] = pack2(a4[e], b4[e]);
            }
            __syncthreads();   /* staged data visible for next iteration */
        }
    }

    /* row-sum reduce across quad, normalize, write */
    rs00 += __shfl_xor_sync(0xffffffffu, rs00, 1);
    rs00 += __shfl_xor_sync(0xffffffffu, rs00, 2);
    rs01 += __shfl_xor_sync(0xffffffffu, rs01, 1);
    rs01 += __shfl_xor_sync(0xffffffffu, rs01, 2);
    rs10 += __shfl_xor_sync(0xffffffffu, rs10, 1);
    rs10 += __shfl_xor_sync(0xffffffffu, rs10, 2);
    rs11 += __shfl_xor_sync(0xffffffffu, rs11, 1);
    rs11 += __shfl_xor_sync(0xffffffffu, rs11, 2);

    #pragma unroll
    for (int mi = 0; mi < 2; mi++) {
        float inv0 = 1.0f / (mi ? rs10 : rs00);
        float inv1 = 1.0f / (mi ? rs11 : rs01);
        float* ob0 = g_attn
            + (size_t)(n * QL + q0 + w * 32 + mi * 16 + g) * ED + h * HD;
        float* ob1 = ob0 + (size_t)8 * ED;
        #pragma unroll
        for (int ds = 0; ds < 8; ds++) {
            *(float2*)(ob0 + ds * 8 + 2 * c) =
                make_float2(Oa[mi][ds][0] * inv0, Oa[mi][ds][1] * inv0);
            *(float2*)(ob1 + ds * 8 + 2 * c) =
                make_float2(Oa[mi][ds][2] * inv1, Oa[mi][ds][3] * inv1);
        }
    }
}

/* ------------- projection Y = X W^T + b (fp16 mma, f32 accum) ------------ */
__global__ __launch_bounds__(256, 2)
void proj_mma(const float* __restrict__ W, const float* __restrict__ bias,
              float* __restrict__ Y)
{
    extern __shared__ uint32_t ps[];
    uint32_t* XH = ps;                       /* [128][36] half2 */
    uint32_t* WS = ps + 128 * PH_PITCH;

    const int tid = threadIdx.x, w = tid >> 5, lane = tid & 31;
    const int g = lane >> 2, c = lane & 3;
    const int wm = w & 3, wn = w >> 2;
    const int m0 = blockIdx.y * 128, n0 = blockIdx.x * 128;
    const float* X = g_attn;

    float D[2][8][4];
    #pragma unroll
    for (int a = 0; a < 2; a++)
        #pragma unroll
        for (int i = 0; i < 8; i++)
            #pragma unroll
            for (int j = 0; j < 4; j++) D[a][i][j] = 0.0f;

    for (int kt = 0; kt < 32; kt++) {
        const int k0 = kt * 32;
        __syncthreads();
        #pragma unroll
        for (int j = 0; j < 4; j++) {
            int flat = tid + 256 * j, r = flat >> 3, c4 = flat & 7;
            float4 xv = *(const float4*)(X + (size_t)(m0 + r) * ED + k0 + c4 * 4);
            uint32_t* dh = XH + r * PH_PITCH + c4 * 2;
            dh[0] = pack2(xv.x, xv.y); dh[1] = pack2(xv.z, xv.w);
            float4 wv = *(const float4*)(W + (size_t)(n0 + r) * ED + k0 + c4 * 4);
            uint32_t* dw = WS + r * PH_PITCH + c4 * 2;
            dw[0] = pack2(wv.x, wv.y); dw[1] = pack2(wv.z, wv.w);
        }
        __syncthreads();

        #pragma unroll
        for (int ks = 0; ks < 2; ks++) {
            uint32_t A[2][4];
            #pragma unroll
            for (int mi = 0; mi < 2; mi++) {
                int rb = wm * 32 + mi * 16;
                const uint32_t* p0 = XH + (rb + g) * PH_PITCH + ks * 8 + c;
                const uint32_t* p1 = XH + (rb + g + 8) * PH_PITCH + ks * 8 + c;
                A[mi][0] = p0[0]; A[mi][2] = p0[4];
                A[mi][1] = p1[0]; A[mi][3] = p1[4];
            }
            #pragma unroll
            for (int ns = 0; ns < 8; ns++) {
                const uint32_t* bp =
                    WS + (wn * 64 + ns * 8 + g) * PH_PITCH + ks * 8 + c;
                uint32_t b0 = bp[0], b1 = bp[4];
                mma16(D[0][ns], A[0], b0, b1);
                mma16(D[1][ns], A[1], b0, b1);
            }
        }
    }

    #pragma unroll
    for (int mi = 0; mi < 2; mi++) {
        int row0 = m0 + wm * 32 + mi * 16 + g;
        #pragma unroll
        for (int ns = 0; ns < 8; ns++) {
            int col = n0 + wn * 64 + ns * 8 + 2 * c;
            float2 bv = *(const float2*)(bias + col);
            *(float2*)(Y + (size_t)row0 * ED + col) =
                make_float2(D[mi][ns][0] + bv.x, D[mi][ns][1] + bv.y);
            *(float2*)(Y + (size_t)(row0 + 8) * ED + col) =
                make_float2(D[mi][ns][2] + bv.x, D[mi][ns][3] + bv.y);
        }
    }
}

/* --------------------------------- launch -------------------------------- */
extern "C" void kernel_launch(void* const* d_in, const int* in_sizes, int n_in,
                              void* d_out, int out_size)
{
    const float* q    = (const float*)d_in[0];
    const float* k    = (const float*)d_in[1];
    const float* v    = (const float*)d_in[2];
    const int*   mask = (const int*)  d_in[3];
    const float* W    = (const float*)d_in[4];
    const float* b    = (const float*)d_in[5];
    float* out = (float*)d_out;

    const int smem_attn = (2 * 64 + 256) * PH_PITCH * 4;   /* 55296 */
    const int smem_proj = 2 * 128 * PH_PITCH * 4;          /* 36864 */
    cudaFuncSetAttribute(attn_mma, cudaFuncAttributeMaxDynamicSharedMemorySize, smem_attn);
    cudaFuncSetAttribute(proj_mma, cudaFuncAttributeMaxDynamicSharedMemorySize, smem_proj);

    maskpack<<<8192, 256>>>(mask);

    dim3 g1(QL / BQ, NBATCH * HEADS);
    attn_mma<<<g1, 256, smem_attn>>>(q, k, v);

    dim3 g2(ED / 128, (NBATCH * QL) / 128);
    proj_mma<<<g2, 256, smem_proj>>>(W, b, out);
}